// round 5
// baseline (speedup 1.0000x reference)
#include <cuda_runtime.h>

#define NB     512
#define NU_PTS 32
#define NV_PTS 128
#define NVQ    32          // v points per block (quarter)
#define NC     16

__global__ __launch_bounds__(256, 6)
void surf_eval_kernel(const float4* __restrict__ ctrl,   // [NB][16][16] of (x,y,z,w)
                      const float4* __restrict__ Nu4,    // [32]
                      const float4* __restrict__ Nv4,    // [128]
                      const int*    __restrict__ uspan,  // [32]
                      const int*    __restrict__ vspan,  // [128]
                      float*        __restrict__ out)    // [NB][32][128][3]
{
    __shared__ float4 sctrl[NC][NC];        // 4 KB
    __shared__ float4 sT[NC][NVQ];          // 8 KB : T[ui][vl] for this v-quarter
    __shared__ float4 sNu[NU_PTS];          // 512 B
    __shared__ float4 sNv[NVQ];             // 512 B
    __shared__ int    sUs[NU_PTS];
    __shared__ int    sVs[NVQ];

    const int tid = threadIdx.x;
    const int b   = blockIdx.x >> 2;        // batch
    const int vq  = blockIdx.x & 3;         // v-quarter: v = vq*32 + vl
    const int vbase = vq * NVQ;

    // ---- load: ctrl tile (256 float4, one per thread), basis + spans ----
    ((float4*)sctrl)[tid] = ctrl[b * 256 + tid];
    if (tid < NVQ) {
        sNv[tid] = Nv4[vbase + tid];
        sVs[tid] = vspan[vbase + tid] - 3;
    } else if (tid < NVQ + NU_PTS) {
        int u = tid - NVQ;
        sNu[u] = Nu4[u];
        sUs[u] = uspan[u] - 3;
    }
    __syncthreads();

    // ---- stage 1: contract over vj (4 sparse terms) ----
    // 16 ui rows x 32 vl = 512 outputs, 256 threads -> 2 iterations
    #pragma unroll
    for (int it = 0; it < 2; ++it) {
        int idx = it * 256 + tid;
        int ui  = idx >> 5;        // 0..15
        int vl  = idx & 31;        // 0..31
        int vs  = sVs[vl];
        float4 nv = sNv[vl];
        float4 c0 = sctrl[ui][vs + 0];
        float4 c1 = sctrl[ui][vs + 1];
        float4 c2 = sctrl[ui][vs + 2];
        float4 c3 = sctrl[ui][vs + 3];
        float4 t;
        t.x = nv.x * c0.x + nv.y * c1.x + nv.z * c2.x + nv.w * c3.x;
        t.y = nv.x * c0.y + nv.y * c1.y + nv.z * c2.y + nv.w * c3.y;
        t.z = nv.x * c0.z + nv.y * c1.z + nv.z * c2.z + nv.w * c3.z;
        t.w = nv.x * c0.w + nv.y * c1.w + nv.z * c2.w + nv.w * c3.w;
        sT[ui][vl] = t;
    }
    __syncthreads();

    // ---- stage 2: rotating register window over sT rows ----
    // thread -> (vl = tid&31, u-eighth = tid>>5 : u in [e*4, e*4+4) )
    // uspan is monotone in u and tid>>5 is warp-uniform, so the window-shift
    // loop is non-divergent and each sT row is loaded exactly once per thread.
    {
        const int vl = tid & 31;
        const int ue = tid >> 5;              // 0..7, uniform within a warp
        const int u0 = ue * 4;

        int r = sUs[u0];                      // current window base row
        float4 t0 = sT[r + 0][vl];
        float4 t1 = sT[r + 1][vl];
        float4 t2 = sT[r + 2][vl];
        float4 t3 = sT[r + 3][vl];

        float* op = out + (((size_t)b * NU_PTS + u0) * NV_PTS + vbase + vl) * 3;

        #pragma unroll
        for (int k = 0; k < 4; ++k) {
            const int u  = u0 + k;
            const int i0 = sUs[u];
            while (r < i0) {                  // warp-uniform shift (0 or 1 typical)
                t0 = t1; t1 = t2; t2 = t3;
                t3 = sT[r + 4][vl];
                ++r;
            }
            float4 nu = sNu[u];
            float x = nu.x * t0.x + nu.y * t1.x + nu.z * t2.x + nu.w * t3.x;
            float y = nu.x * t0.y + nu.y * t1.y + nu.z * t2.y + nu.w * t3.y;
            float z = nu.x * t0.z + nu.y * t1.z + nu.z * t2.z + nu.w * t3.z;
            float w = nu.x * t0.w + nu.y * t1.w + nu.z * t2.w + nu.w * t3.w;

            float rcp = __fdividef(1.0f, fmaxf(w, 1e-8f));
            op[0] = x * rcp;
            op[1] = y * rcp;
            op[2] = z * rcp;
            op += NV_PTS * 3;                 // next u row
        }
    }
}

extern "C" void kernel_launch(void* const* d_in, const int* in_sizes, int n_in,
                              void* d_out, int out_size)
{
    const float4* ctrl  = (const float4*)d_in[0];
    const float4* Nu4   = (const float4*)d_in[1];
    const float4* Nv4   = (const float4*)d_in[2];
    const int*    uspan = (const int*)d_in[3];
    const int*    vspan = (const int*)d_in[4];
    float*        out   = (float*)d_out;

    surf_eval_kernel<<<NB * 4, 256>>>(ctrl, Nu4, Nv4, uspan, vspan, out);
}

// round 6
// speedup vs baseline: 1.0435x; 1.0435x over previous
#include <cuda_runtime.h>

#define NB     512
#define NU_PTS 32
#define NV_PTS 128
#define NVH    64          // v points per block (half)
#define NC     16

__global__ __launch_bounds__(256, 6)
void surf_eval_kernel(const float4* __restrict__ ctrl,   // [NB][16][16] of (x,y,z,w)
                      const float4* __restrict__ Nu4,    // [32]
                      const float4* __restrict__ Nv4,    // [128]
                      const int*    __restrict__ uspan,  // [32]
                      const int*    __restrict__ vspan,  // [128]
                      float*        __restrict__ out)    // [NB][32][128][3]
{
    __shared__ float4 sctrl[NC][NC];        // 4 KB
    __shared__ float4 sT[NC][NVH];          // 16 KB : T[ui][vl] for this v-half
    __shared__ float4 sNu[NU_PTS];          // 512 B
    __shared__ float4 sNv[NVH];             // 1 KB
    __shared__ int    sUs[NU_PTS];
    __shared__ int    sVs[NVH];

    const int tid = threadIdx.x;
    const int b   = blockIdx.x >> 1;        // batch
    const int vh  = blockIdx.x & 1;         // v-half: v = vh*64 + vl
    const int vbase = vh * NVH;

    // ---- load: ctrl tile (256 float4, one per thread), basis + spans ----
    ((float4*)sctrl)[tid] = ctrl[b * 256 + tid];
    if (tid < NVH) {
        sNv[tid] = Nv4[vbase + tid];
        sVs[tid] = vspan[vbase + tid] - 3;
    } else if (tid < NVH + NU_PTS) {
        int u = tid - NVH;
        sNu[u] = Nu4[u];
        sUs[u] = uspan[u] - 3;
    }
    __syncthreads();

    // ---- stage 1: contract over vj (4 sparse terms) ----
    // 16 ui rows x 64 vl = 1024 outputs, 256 threads -> 4 iterations
    #pragma unroll
    for (int it = 0; it < 4; ++it) {
        int idx = it * 256 + tid;
        int ui  = idx >> 6;        // 0..15
        int vl  = idx & 63;        // 0..63
        int vs  = sVs[vl];
        float4 nv = sNv[vl];
        float4 c0 = sctrl[ui][vs + 0];
        float4 c1 = sctrl[ui][vs + 1];
        float4 c2 = sctrl[ui][vs + 2];
        float4 c3 = sctrl[ui][vs + 3];
        float4 t;
        t.x = nv.x * c0.x + nv.y * c1.x + nv.z * c2.x + nv.w * c3.x;
        t.y = nv.x * c0.y + nv.y * c1.y + nv.z * c2.y + nv.w * c3.y;
        t.z = nv.x * c0.z + nv.y * c1.z + nv.z * c2.z + nv.w * c3.z;
        t.w = nv.x * c0.w + nv.y * c1.w + nv.z * c2.w + nv.w * c3.w;
        sT[ui][vl] = t;
    }
    __syncthreads();

    // ---- stage 2: rotating register window over sT rows ----
    // thread -> (vl = tid&63, u-quarter = tid>>6 : u in [q*8, q*8+8) )
    // uspan is monotone in u and tid>>6 is warp-uniform, so the window-shift
    // loop is non-divergent and each sT row is loaded exactly once per thread.
    {
        const int vl = tid & 63;
        const int uq = tid >> 6;              // 0..3, uniform within a warp
        const int u0 = uq * 8;

        int r = sUs[u0];                      // current window base row
        float4 t0 = sT[r + 0][vl];
        float4 t1 = sT[r + 1][vl];
        float4 t2 = sT[r + 2][vl];
        float4 t3 = sT[r + 3][vl];

        // 32-bit offset arithmetic (output < 2^31 elements) to save registers
        unsigned o = (((unsigned)b * NU_PTS + u0) * NV_PTS + vbase + vl) * 3;

        #pragma unroll
        for (int k = 0; k < 8; ++k) {
            const int u  = u0 + k;
            const int i0 = sUs[u];
            while (r < i0) {                  // warp-uniform shift (0 or 1 typical)
                t0 = t1; t1 = t2; t2 = t3;
                t3 = sT[r + 4][vl];
                ++r;
            }
            float4 nu = sNu[u];
            float x = nu.x * t0.x + nu.y * t1.x + nu.z * t2.x + nu.w * t3.x;
            float y = nu.x * t0.y + nu.y * t1.y + nu.z * t2.y + nu.w * t3.y;
            float z = nu.x * t0.z + nu.y * t1.z + nu.z * t2.z + nu.w * t3.z;
            float w = nu.x * t0.w + nu.y * t1.w + nu.z * t2.w + nu.w * t3.w;

            float rcp = __fdividef(1.0f, fmaxf(w, 1e-8f));
            out[o + 0] = x * rcp;
            out[o + 1] = y * rcp;
            out[o + 2] = z * rcp;
            o += NV_PTS * 3;                  // next u row
        }
    }
}

extern "C" void kernel_launch(void* const* d_in, const int* in_sizes, int n_in,
                              void* d_out, int out_size)
{
    const float4* ctrl  = (const float4*)d_in[0];
    const float4* Nu4   = (const float4*)d_in[1];
    const float4* Nv4   = (const float4*)d_in[2];
    const int*    uspan = (const int*)d_in[3];
    const int*    vspan = (const int*)d_in[4];
    float*        out   = (float*)d_out;

    surf_eval_kernel<<<NB * 2, 256>>>(ctrl, Nu4, Nv4, uspan, vspan, out);
}